// round 2
// baseline (speedup 1.0000x reference)
#include <cuda_runtime.h>
#include <math.h>
#include <stdint.h>

#define NN 50000
#define NE 800000
#define FIN 128
#define D1 256
#define D2 128
#define KC 32

// ---------------- scratch (device globals; no allocation allowed) ----------------
__device__ __align__(16) float g_xw[(size_t)NN * D1];    // X @ W1
__device__ __align__(16) float g_H[(size_t)NN * D1];     // GCN output
__device__ __align__(16) float g_abs[(size_t)NN * D2];   // tanh(H@fc1W+b)
__device__ __align__(16) float g_S[(size_t)NN * KC];     // softmax assign
__device__ __align__(16) float g_LS[(size_t)NN * KC];    // L @ S
__device__ int   g_deg_in[NN], g_deg_out[NN];
__device__ int   g_off_in[NN + 1], g_off_out[NN + 1];
__device__ int   g_cur_in[NN], g_cur_out[NN];
__device__ int   g_src_in[NE];             // CSR by target: source ids
__device__ int   g_dst_out[NE];            // CSR by source: target ids
__device__ float g_dinv1[NN], g_dinv2[NN];
__device__ float g_adj[KC * KC];
__device__ float g_emb[D1];

// ---------------- init / graph structure ----------------
__global__ void k_zero() {
    int i = blockIdx.x * blockDim.x + threadIdx.x;
    int stride = gridDim.x * blockDim.x;
    for (int j = i; j < NN; j += stride) {
        g_deg_in[j] = 0; g_deg_out[j] = 0;
        g_cur_in[j] = 0; g_cur_out[j] = 0;
    }
    if (i < KC * KC) g_adj[i] = 0.f;
    if (i < D1) g_emb[i] = 0.f;
}

__global__ void k_degree(const int* __restrict__ e) {
    int i = blockIdx.x * blockDim.x + threadIdx.x;
    int stride = gridDim.x * blockDim.x;
    for (int j = i; j < NE; j += stride) {
        int r = e[j];
        int c = e[NE + j];
        atomicAdd(&g_deg_out[r], 1);
        atomicAdd(&g_deg_in[c], 1);
    }
}

// single-block exclusive scan over 50000 counts (which=0: in, which=1: out)
__global__ void k_scan(int which) {
    const int* cnt = which ? g_deg_out : g_deg_in;
    int* off = which ? g_off_out : g_off_in;
    __shared__ int sh[1024];
    int t = threadIdx.x;
    int chunk = (NN + 1023) / 1024;
    int s0 = t * chunk;
    int s1 = min(s0 + chunk, NN);
    int s = 0;
    for (int i = s0; i < s1; i++) s += cnt[i];
    sh[t] = s;
    __syncthreads();
    for (int d = 1; d < 1024; d <<= 1) {
        int v = (t >= d) ? sh[t - d] : 0;
        __syncthreads();
        sh[t] += v;
        __syncthreads();
    }
    int run = sh[t] - s; // exclusive
    for (int i = s0; i < s1; i++) { off[i] = run; run += cnt[i]; }
    if (t == 1023) off[NN] = sh[1023];
}

__global__ void k_dinv() {
    int i = blockIdx.x * blockDim.x + threadIdx.x;
    int stride = gridDim.x * blockDim.x;
    for (int j = i; j < NN; j += stride) {
        g_dinv1[j] = rsqrtf((float)(g_deg_in[j] + 1)); // self-loop included
        int d = g_deg_out[j];
        g_dinv2[j] = (d > 0) ? rsqrtf((float)d) : 0.f;
    }
}

__global__ void k_fill(const int* __restrict__ e) {
    int i = blockIdx.x * blockDim.x + threadIdx.x;
    int stride = gridDim.x * blockDim.x;
    for (int j = i; j < NE; j += stride) {
        int r = e[j];
        int c = e[NE + j];
        int p = atomicAdd(&g_cur_in[c], 1);
        g_src_in[g_off_in[c] + p] = r;
        int q = atomicAdd(&g_cur_out[r], 1);
        g_dst_out[g_off_out[r] + q] = c;
    }
}

// ---------------- SGEMM core: C = act(A[M,K] @ B[K,N] + bias) ----------------
// 64x64 tile, BK=16, 256 threads, 4x4 per-thread microtile.
template <int ACT>
__device__ __forceinline__ void sgemm_body(
    const float* __restrict__ A, const float* __restrict__ B,
    const float* __restrict__ bias, float* __restrict__ C,
    int M, int N, int K)
{
    __shared__ float As[16][68]; // [k][m], padded
    __shared__ float Bs[16][64]; // [k][n]
    int tid = threadIdx.x;
    int m0 = blockIdx.y * 64, n0 = blockIdx.x * 64;
    int tx = tid % 16, ty = tid / 16;

    int alr = tid / 4;            // 0..63 row in tile
    int alc = (tid % 4) * 4;      // k offset
    int bkr = tid / 16;           // 0..15 k row
    int bnc = (tid % 16) * 4;     // n offset

    float acc[4][4];
    #pragma unroll
    for (int u = 0; u < 4; u++)
        #pragma unroll
        for (int v = 0; v < 4; v++) acc[u][v] = 0.f;

    for (int k0 = 0; k0 < K; k0 += 16) {
        float4 av = make_float4(0.f, 0.f, 0.f, 0.f);
        int arow = m0 + alr;
        if (arow < M) av = *(const float4*)&A[(size_t)arow * K + k0 + alc];
        As[alc + 0][alr] = av.x;
        As[alc + 1][alr] = av.y;
        As[alc + 2][alr] = av.z;
        As[alc + 3][alr] = av.w;
        float4 bv = *(const float4*)&B[(size_t)(k0 + bkr) * N + n0 + bnc];
        *(float4*)&Bs[bkr][bnc] = bv;
        __syncthreads();
        #pragma unroll
        for (int k = 0; k < 16; k++) {
            float4 ar = *(const float4*)&As[k][ty * 4];
            float4 br = *(const float4*)&Bs[k][tx * 4];
            float a4[4] = {ar.x, ar.y, ar.z, ar.w};
            float b4[4] = {br.x, br.y, br.z, br.w};
            #pragma unroll
            for (int u = 0; u < 4; u++)
                #pragma unroll
                for (int v = 0; v < 4; v++)
                    acc[u][v] += a4[u] * b4[v];
        }
        __syncthreads();
    }
    #pragma unroll
    for (int u = 0; u < 4; u++) {
        int m = m0 + ty * 4 + u;
        if (m >= M) continue;
        #pragma unroll
        for (int v = 0; v < 4; v++) {
            int n = n0 + tx * 4 + v;
            float val = acc[u][v] + (bias ? bias[n] : 0.f);
            if (ACT == 1) val = tanhf(val);
            C[(size_t)m * N + n] = val;
        }
    }
}

// xw = feat @ W1 (no bias)
__global__ __launch_bounds__(256) void k_gemm_xw(
    const float* __restrict__ feat, const float* __restrict__ W1)
{
    sgemm_body<0>(feat, W1, nullptr, g_xw, NN, D1, FIN);
}

// abs = tanh(H @ fc1W + fc1b)
__global__ __launch_bounds__(256) void k_gemm_abs(
    const float* __restrict__ fc1W, const float* __restrict__ fc1b)
{
    sgemm_body<1>(g_H, fc1W, fc1b, g_abs, NN, D2, D1);
}

// ---------------- GCN aggregation: H[i] = dinv1[i]*(sum dinv1[s]*xw[s] + dinv1[i]*xw[i]) + b1 ----------------
__global__ __launch_bounds__(256) void k_gcn_agg(const float* __restrict__ b1) {
    int i = blockIdx.x;
    int t = threadIdx.x; // 256 = D1
    float di = g_dinv1[i];
    float acc = di * g_xw[(size_t)i * D1 + t]; // self loop
    int s0 = g_off_in[i], s1 = g_off_in[i + 1];
    for (int idx = s0; idx < s1; idx++) {
        int s = g_src_in[idx];
        acc += g_dinv1[s] * g_xw[(size_t)s * D1 + t];
    }
    g_H[(size_t)i * D1 + t] = di * acc + b1[t];
}

// ---------------- fused fc2 + softmax: S = softmax(abs @ fc2W + fc2b) ----------------
__global__ __launch_bounds__(256) void k_fc2_softmax(
    const float* __restrict__ W, const float* __restrict__ b)
{
    __shared__ float Ws[D2 * KC];
    __shared__ float bs[KC];
    int tid = threadIdx.x;
    for (int j = tid; j < D2 * KC; j += blockDim.x) Ws[j] = W[j];
    if (tid < KC) bs[tid] = b[tid];
    __syncthreads();
    int lane = tid & 31, warp = tid >> 5;
    int nwarps = (blockDim.x >> 5) * gridDim.x;
    for (int i = blockIdx.x * (blockDim.x >> 5) + warp; i < NN; i += nwarps) {
        float areg[4];
        #pragma unroll
        for (int j = 0; j < 4; j++) areg[j] = g_abs[(size_t)i * D2 + j * 32 + lane];
        float acc = bs[lane];
        #pragma unroll
        for (int j = 0; j < 4; j++)
            #pragma unroll
            for (int d = 0; d < 32; d++) {
                float a = __shfl_sync(0xffffffffu, areg[j], d);
                acc += a * Ws[(j * 32 + d) * KC + lane];
            }
        float m = acc;
        #pragma unroll
        for (int o = 16; o > 0; o >>= 1) m = fmaxf(m, __shfl_xor_sync(0xffffffffu, m, o));
        float e = expf(acc - m);
        float s = e;
        #pragma unroll
        for (int o = 16; o > 0; o >>= 1) s += __shfl_xor_sync(0xffffffffu, s, o);
        g_S[(size_t)i * KC + lane] = e / s;
    }
}

// ---------------- Laplacian: LS[i] = S[i] - dinv2[i] * sum dinv2[c]*S[c] ----------------
__global__ __launch_bounds__(256) void k_lap() {
    int tid = blockIdx.x * blockDim.x + threadIdx.x;
    int lane = tid & 31;
    int i = tid >> 5;
    if (i >= NN) return;
    float acc = g_S[(size_t)i * KC + lane];
    float di = g_dinv2[i];
    int s0 = g_off_out[i], s1 = g_off_out[i + 1];
    for (int idx = s0; idx < s1; idx++) {
        int c = g_dst_out[idx];
        acc -= di * g_dinv2[c] * g_S[(size_t)c * KC + lane];
    }
    g_LS[(size_t)i * KC + lane] = acc;
}

// ---------------- new_adj = S^T @ LS (32x32 reduction over nodes) ----------------
__global__ __launch_bounds__(256) void k_adj() {
    __shared__ float sh[8][KC * KC]; // 32 KB
    int tid = threadIdx.x, lane = tid & 31, w = tid >> 5;
    float acc[32];
    #pragma unroll
    for (int a = 0; a < 32; a++) acc[a] = 0.f;
    int gw = blockIdx.x * 8 + w, tw = gridDim.x * 8;
    for (int i = gw; i < NN; i += tw) {
        float sv = g_S[(size_t)i * 32 + lane];
        float lv = g_LS[(size_t)i * 32 + lane];
        #pragma unroll
        for (int a = 0; a < 32; a++) {
            float sa = __shfl_sync(0xffffffffu, sv, a);
            acc[a] += sa * lv;
        }
    }
    #pragma unroll
    for (int a = 0; a < 32; a++) sh[w][a * 32 + lane] = acc[a];
    __syncthreads();
    for (int j = tid; j < KC * KC; j += blockDim.x) {
        float s = 0.f;
        #pragma unroll
        for (int w2 = 0; w2 < 8; w2++) s += sh[w2][j];
        atomicAdd(&g_adj[j], s);
    }
}

// ---------------- column sum of H (graph embedding uses rowsum(S)==1) ----------------
__global__ __launch_bounds__(256) void k_colsum() {
    int t = threadIdx.x; // 256 = D1
    float acc = 0.f;
    for (int i = blockIdx.x; i < NN; i += gridDim.x)
        acc += g_H[(size_t)i * D1 + t];
    atomicAdd(&g_emb[t], acc);
}

// ---------------- finalize: embedding/32 and pos_penalty ----------------
__global__ void k_final(float* __restrict__ out, int out_size) {
    int t = threadIdx.x; // 256
    if (t < D1 && t < out_size) out[t] = g_emb[t] * (1.f / 32.f);
    if (t < 32) {
        float rs = 0.f;
        #pragma unroll
        for (int b = 0; b < 32; b++) rs += fabsf(g_adj[t * 32 + b]);
        float d = g_adj[t * 33] / fmaxf(rs, 1e-12f);
        float contrib = (d - 1.f) * (d - 1.f) + 31.f * d * d;
        #pragma unroll
        for (int o = 16; o > 0; o >>= 1) contrib += __shfl_xor_sync(0xffffffffu, contrib, o);
        if (t == 0 && out_size > D1) out[D1] = contrib * (1.f / 1024.f);
    }
}

// ---------------- launch ----------------
extern "C" void kernel_launch(void* const* d_in, const int* in_sizes, int n_in,
                              void* d_out, int out_size) {
    const float* feat  = (const float*)d_in[0];
    const int*   edges = (const int*)d_in[1];   // (2, E) int32 (JAX x64 disabled)
    // d_in[2] = W1, d_in[3] = b1, d_in[4] = fc1_W, d_in[5] = fc1_b,
    // d_in[6] = fc2_W, d_in[7] = fc2_b
    const float* W1   = (const float*)d_in[2];
    const float* b1   = (const float*)d_in[3];
    const float* fc1W = (const float*)d_in[4];
    const float* fc1b = (const float*)d_in[5];
    const float* fc2W = (const float*)d_in[6];
    const float* fc2b = (const float*)d_in[7];
    float* out = (float*)d_out;

    k_zero<<<256, 256>>>();
    k_degree<<<1024, 256>>>(edges);
    k_scan<<<1, 1024>>>(0);
    k_scan<<<1, 1024>>>(1);
    k_dinv<<<256, 256>>>();
    k_fill<<<1024, 256>>>(edges);

    {
        dim3 grid(D1 / 64, (NN + 63) / 64);
        k_gemm_xw<<<grid, 256>>>(feat, W1);
    }
    k_gcn_agg<<<NN, 256>>>(b1);
    {
        dim3 grid(D2 / 64, (NN + 63) / 64);
        k_gemm_abs<<<grid, 256>>>(fc1W, fc1b);
    }
    k_fc2_softmax<<<296, 256>>>(fc2W, fc2b);
    k_lap<<<(NN * 32 + 255) / 256, 256>>>();
    k_adj<<<148, 256>>>();
    k_colsum<<<512, 256>>>();
    k_final<<<1, 256>>>(out, out_size);
}

// round 3
// speedup vs baseline: 1.9881x; 1.9881x over previous
#include <cuda_runtime.h>
#include <math.h>
#include <stdint.h>

#define NN 50000
#define NE 800000
#define FIN 128
#define D1 256
#define D2 128
#define KC 32

// ---------------- scratch (device globals; no allocation allowed) ----------------
__device__ __align__(16) float g_aggX[(size_t)NN * FIN];  // (A+I)-normalized agg of features
__device__ __align__(16) float g_H[(size_t)NN * D1];      // GCN output
__device__ __align__(16) float g_abs[(size_t)NN * D2];    // tanh(H@fc1W+b)
__device__ __align__(16) float g_S[(size_t)NN * KC];      // softmax assign
__device__ __align__(16) float g_LS[(size_t)NN * KC];     // L @ S
__device__ int   g_deg_in[NN], g_deg_out[NN];
__device__ int   g_off_in[NN + 1], g_off_out[NN + 1];
__device__ int   g_cur_in[NN], g_cur_out[NN];
__device__ int   g_src_in[NE];             // CSR by target: source ids
__device__ int   g_dst_out[NE];            // CSR by source: target ids
__device__ float g_dinv1[NN], g_dinv2[NN];
__device__ float g_adj[KC * KC];
__device__ float g_emb[D1];

// ---------------- init ----------------
__global__ void k_zero() {
    int i = blockIdx.x * blockDim.x + threadIdx.x;
    int stride = gridDim.x * blockDim.x;
    for (int j = i; j < NN; j += stride) {
        g_deg_in[j] = 0; g_deg_out[j] = 0;
        g_cur_in[j] = 0; g_cur_out[j] = 0;
    }
    if (i < KC * KC) g_adj[i] = 0.f;
    if (i < D1) g_emb[i] = 0.f;
}

__global__ void k_degree(const int* __restrict__ e) {
    int i = blockIdx.x * blockDim.x + threadIdx.x;
    int stride = gridDim.x * blockDim.x;
    for (int j = i; j < NE; j += stride) {
        atomicAdd(&g_deg_out[e[j]], 1);
        atomicAdd(&g_deg_in[e[NE + j]], 1);
    }
}

// ---- fast tiled block scan: block 0 scans deg_in, block 1 scans deg_out ----
__global__ __launch_bounds__(1024) void k_scan2() {
    const int* cnt = blockIdx.x ? g_deg_out : g_deg_in;
    int* off = blockIdx.x ? g_off_out : g_off_in;
    __shared__ int wsum[32];
    __shared__ int carry;
    int t = threadIdx.x;
    int lane = t & 31, w = t >> 5;
    if (t == 0) carry = 0;
    __syncthreads();
    for (int base = 0; base < NN; base += 1024) {
        int idx = base + t;
        int v = (idx < NN) ? cnt[idx] : 0;
        int x = v;
        #pragma unroll
        for (int o = 1; o < 32; o <<= 1) {
            int y = __shfl_up_sync(0xffffffffu, x, o);
            if (lane >= o) x += y;
        }
        if (lane == 31) wsum[w] = x;
        __syncthreads();
        if (w == 0) {
            int s = wsum[lane];
            #pragma unroll
            for (int o = 1; o < 32; o <<= 1) {
                int y = __shfl_up_sync(0xffffffffu, s, o);
                if (lane >= o) s += y;
            }
            wsum[lane] = s;
        }
        __syncthreads();
        int incl = x + (w ? wsum[w - 1] : 0);
        if (idx < NN) off[idx] = carry + incl - v;
        int total = wsum[31];
        __syncthreads();
        if (t == 0) carry += total;
        __syncthreads();
    }
    if (t == 0) off[NN] = carry;
}

__global__ void k_dinv() {
    int i = blockIdx.x * blockDim.x + threadIdx.x;
    int stride = gridDim.x * blockDim.x;
    for (int j = i; j < NN; j += stride) {
        g_dinv1[j] = rsqrtf((float)(g_deg_in[j] + 1)); // self-loop included
        int d = g_deg_out[j];
        g_dinv2[j] = (d > 0) ? rsqrtf((float)d) : 0.f;
    }
}

__global__ void k_fill(const int* __restrict__ e) {
    int i = blockIdx.x * blockDim.x + threadIdx.x;
    int stride = gridDim.x * blockDim.x;
    for (int j = i; j < NE; j += stride) {
        int r = e[j];
        int c = e[NE + j];
        int p = atomicAdd(&g_cur_in[c], 1);
        g_src_in[g_off_in[c] + p] = r;
        int q = atomicAdd(&g_cur_out[r], 1);
        g_dst_out[g_off_out[r] + q] = c;
    }
}

// ---------------- feature aggregation: aggX[i] = di*(sum ds*X[s] + di*X[i]) ----------------
__global__ __launch_bounds__(256) void k_agg(const float* __restrict__ X) {
    int i = blockIdx.x * 8 + (threadIdx.x >> 5);
    int lane = threadIdx.x & 31;
    if (i >= NN) return;
    float di = g_dinv1[i];
    const float4* X4 = (const float4*)X;
    float4 x = X4[(size_t)i * 32 + lane];
    float4 acc = make_float4(di * x.x, di * x.y, di * x.z, di * x.w);
    int s0 = g_off_in[i], s1 = g_off_in[i + 1];
    for (int idx = s0; idx < s1; idx++) {
        int s = g_src_in[idx];
        float ds = g_dinv1[s];
        float4 xs = X4[(size_t)s * 32 + lane];
        acc.x += ds * xs.x; acc.y += ds * xs.y;
        acc.z += ds * xs.z; acc.w += ds * xs.w;
    }
    float4 o = make_float4(di * acc.x, di * acc.y, di * acc.z, di * acc.w);
    ((float4*)g_aggX)[(size_t)i * 32 + lane] = o;
}

// ---------------- SGEMM: 128x128 tile, BK=8, 256 threads, 8x8 microtile ----------------
template <int ACT>
__device__ __forceinline__ void sgemm128(
    const float* __restrict__ A, const float* __restrict__ B,
    const float* __restrict__ bias, float* __restrict__ C,
    int M, int N, int K)
{
    __shared__ float As[8][128];
    __shared__ float Bs[8][128];
    int tid = threadIdx.x;
    int m0 = blockIdx.y * 128, n0 = blockIdx.x * 128;
    int tx = tid % 16, ty = tid / 16;

    int ar = tid >> 1, ak = (tid & 1) * 4;   // A: row 0..127, k 0..7
    int bk = tid >> 5, bn = (tid & 31) * 4;  // B: k 0..7, n 0..127

    float acc[8][8];
    #pragma unroll
    for (int i = 0; i < 8; i++)
        #pragma unroll
        for (int j = 0; j < 8; j++) acc[i][j] = 0.f;

    for (int k0 = 0; k0 < K; k0 += 8) {
        float4 av = make_float4(0.f, 0.f, 0.f, 0.f);
        if (m0 + ar < M) av = *(const float4*)&A[(size_t)(m0 + ar) * K + k0 + ak];
        As[ak + 0][ar] = av.x; As[ak + 1][ar] = av.y;
        As[ak + 2][ar] = av.z; As[ak + 3][ar] = av.w;
        float4 bv = *(const float4*)&B[(size_t)(k0 + bk) * N + n0 + bn];
        *(float4*)&Bs[bk][bn] = bv;
        __syncthreads();
        #pragma unroll
        for (int k = 0; k < 8; k++) {
            float4 a0 = *(const float4*)&As[k][ty * 8];
            float4 a1 = *(const float4*)&As[k][ty * 8 + 4];
            float4 b0 = *(const float4*)&Bs[k][tx * 8];
            float4 b1 = *(const float4*)&Bs[k][tx * 8 + 4];
            float aR[8] = {a0.x, a0.y, a0.z, a0.w, a1.x, a1.y, a1.z, a1.w};
            float bR[8] = {b0.x, b0.y, b0.z, b0.w, b1.x, b1.y, b1.z, b1.w};
            #pragma unroll
            for (int i = 0; i < 8; i++)
                #pragma unroll
                for (int j = 0; j < 8; j++)
                    acc[i][j] += aR[i] * bR[j];
        }
        __syncthreads();
    }

    float bloc[8];
    #pragma unroll
    for (int j = 0; j < 8; j++) bloc[j] = bias ? bias[n0 + tx * 8 + j] : 0.f;
    #pragma unroll
    for (int i = 0; i < 8; i++) {
        int m = m0 + ty * 8 + i;
        if (m >= M) continue;
        float4 r0, r1;
        float v[8];
        #pragma unroll
        for (int j = 0; j < 8; j++) {
            float val = acc[i][j] + bloc[j];
            if (ACT == 1) val = tanhf(val);
            v[j] = val;
        }
        r0 = make_float4(v[0], v[1], v[2], v[3]);
        r1 = make_float4(v[4], v[5], v[6], v[7]);
        *(float4*)&C[(size_t)m * N + n0 + tx * 8] = r0;
        *(float4*)&C[(size_t)m * N + n0 + tx * 8 + 4] = r1;
    }
}

// H = aggX @ W1 + b1
__global__ __launch_bounds__(256) void k_gemm1(
    const float* __restrict__ W1, const float* __restrict__ b1)
{
    sgemm128<0>(g_aggX, W1, b1, g_H, NN, D1, FIN);
}

// abs = tanh(H @ fc1W + fc1b)
__global__ __launch_bounds__(256) void k_gemm2(
    const float* __restrict__ fc1W, const float* __restrict__ fc1b)
{
    sgemm128<1>(g_H, fc1W, fc1b, g_abs, NN, D2, D1);
}

// ---------------- fused fc2 + softmax ----------------
__global__ __launch_bounds__(256) void k_fc2_softmax(
    const float* __restrict__ W, const float* __restrict__ b)
{
    __shared__ float Ws[D2 * KC];
    __shared__ float bs[KC];
    int tid = threadIdx.x;
    for (int j = tid; j < D2 * KC; j += blockDim.x) Ws[j] = W[j];
    if (tid < KC) bs[tid] = b[tid];
    __syncthreads();
    int lane = tid & 31, warp = tid >> 5;
    int nwarps = (blockDim.x >> 5) * gridDim.x;
    for (int i = blockIdx.x * (blockDim.x >> 5) + warp; i < NN; i += nwarps) {
        float areg[4];
        #pragma unroll
        for (int j = 0; j < 4; j++) areg[j] = g_abs[(size_t)i * D2 + j * 32 + lane];
        float acc = bs[lane];
        #pragma unroll
        for (int j = 0; j < 4; j++)
            #pragma unroll
            for (int d = 0; d < 32; d++) {
                float a = __shfl_sync(0xffffffffu, areg[j], d);
                acc += a * Ws[(j * 32 + d) * KC + lane];
            }
        float m = acc;
        #pragma unroll
        for (int o = 16; o > 0; o >>= 1) m = fmaxf(m, __shfl_xor_sync(0xffffffffu, m, o));
        float e = expf(acc - m);
        float s = e;
        #pragma unroll
        for (int o = 16; o > 0; o >>= 1) s += __shfl_xor_sync(0xffffffffu, s, o);
        g_S[(size_t)i * KC + lane] = e / s;
    }
}

// ---------------- Laplacian: LS[i] = S[i] - dinv2[i]*sum dinv2[c]*S[c] ----------------
__global__ __launch_bounds__(256) void k_lap() {
    int tid = blockIdx.x * blockDim.x + threadIdx.x;
    int lane = tid & 31;
    int i = tid >> 5;
    if (i >= NN) return;
    float acc = g_S[(size_t)i * KC + lane];
    float di = g_dinv2[i];
    int s0 = g_off_out[i], s1 = g_off_out[i + 1];
    for (int idx = s0; idx < s1; idx++) {
        int c = g_dst_out[idx];
        acc -= di * g_dinv2[c] * g_S[(size_t)c * KC + lane];
    }
    g_LS[(size_t)i * KC + lane] = acc;
}

// ---------------- new_adj = S^T @ LS ----------------
__global__ __launch_bounds__(256) void k_adj() {
    __shared__ float sh[8][KC * KC];
    int tid = threadIdx.x, lane = tid & 31, w = tid >> 5;
    float acc[32];
    #pragma unroll
    for (int a = 0; a < 32; a++) acc[a] = 0.f;
    int gw = blockIdx.x * 8 + w, tw = gridDim.x * 8;
    for (int i = gw; i < NN; i += tw) {
        float sv = g_S[(size_t)i * 32 + lane];
        float lv = g_LS[(size_t)i * 32 + lane];
        #pragma unroll
        for (int a = 0; a < 32; a++) {
            float sa = __shfl_sync(0xffffffffu, sv, a);
            acc[a] += sa * lv;
        }
    }
    #pragma unroll
    for (int a = 0; a < 32; a++) sh[w][a * 32 + lane] = acc[a];
    __syncthreads();
    for (int j = tid; j < KC * KC; j += blockDim.x) {
        float s = 0.f;
        #pragma unroll
        for (int w2 = 0; w2 < 8; w2++) s += sh[w2][j];
        atomicAdd(&g_adj[j], s);
    }
}

// ---------------- column sum of H ----------------
__global__ __launch_bounds__(256) void k_colsum() {
    int t = threadIdx.x; // 256 = D1
    float acc = 0.f;
    for (int i = blockIdx.x; i < NN; i += gridDim.x)
        acc += g_H[(size_t)i * D1 + t];
    atomicAdd(&g_emb[t], acc);
}

// ---------------- finalize ----------------
__global__ void k_final(float* __restrict__ out, int out_size) {
    int t = threadIdx.x;
    if (t < D1 && t < out_size) out[t] = g_emb[t] * (1.f / 32.f);
    if (t < 32) {
        float rs = 0.f;
        #pragma unroll
        for (int b = 0; b < 32; b++) rs += fabsf(g_adj[t * 32 + b]);
        float d = g_adj[t * 33] / fmaxf(rs, 1e-12f);
        float contrib = (d - 1.f) * (d - 1.f) + 31.f * d * d;
        #pragma unroll
        for (int o = 16; o > 0; o >>= 1) contrib += __shfl_xor_sync(0xffffffffu, contrib, o);
        if (t == 0 && out_size > D1) out[D1] = contrib * (1.f / 1024.f);
    }
}

// ---------------- launch ----------------
extern "C" void kernel_launch(void* const* d_in, const int* in_sizes, int n_in,
                              void* d_out, int out_size) {
    const float* feat  = (const float*)d_in[0];
    const int*   edges = (const int*)d_in[1];   // (2, E) int32
    const float* W1    = (const float*)d_in[2];
    const float* b1    = (const float*)d_in[3];
    const float* fc1W  = (const float*)d_in[4];
    const float* fc1b  = (const float*)d_in[5];
    const float* fc2W  = (const float*)d_in[6];
    const float* fc2b  = (const float*)d_in[7];
    float* out = (float*)d_out;

    k_zero<<<256, 256>>>();
    k_degree<<<1024, 256>>>(edges);
    k_scan2<<<2, 1024>>>();
    k_dinv<<<256, 256>>>();
    k_fill<<<1024, 256>>>(edges);

    k_agg<<<(NN + 7) / 8, 256>>>(feat);
    {
        dim3 grid(D1 / 128, (NN + 127) / 128);
        k_gemm1<<<grid, 256>>>(W1, b1);
    }
    {
        dim3 grid(D2 / 128, (NN + 127) / 128);
        k_gemm2<<<grid, 256>>>(fc1W, fc1b);
    }
    k_fc2_softmax<<<296, 256>>>(fc2W, fc2b);
    k_lap<<<(NN * 32 + 255) / 256, 256>>>();
    k_adj<<<148, 256>>>();
    k_colsum<<<512, 256>>>();
    k_final<<<1, 256>>>(out, out_size);
}

// round 4
// speedup vs baseline: 2.6966x; 1.3563x over previous
#include <cuda_runtime.h>
#include <math.h>
#include <stdint.h>

#define NN 50000
#define NE 800000
#define FIN 128
#define D1 256
#define D2 128
#define KC 32

// ---------------- scratch (device globals) ----------------
__device__ __align__(16) float g_aggX[(size_t)NN * FIN];  // normalized (A+I) agg of features
__device__ __align__(16) float g_abs[(size_t)NN * D2];    // tanh(aggX@Wc+bc)
__device__ __align__(16) float g_S[(size_t)NN * KC];      // softmax assign
__device__ __align__(16) float g_LS[(size_t)NN * KC];     // L @ S
__device__ __align__(16) float g_Wc[FIN * D2];            // W1 @ fc1W  (128x128)
__device__ float g_bc[D2];                                 // b1 @ fc1W + fc1b
__device__ float g_cs[FIN];                                // colsum(aggX)
__device__ int   g_deg_in[NN], g_deg_out[NN];
__device__ int   g_off_in[NN + 1], g_off_out[NN + 1];
__device__ int   g_cur_in[NN], g_cur_out[NN];
__device__ int   g_src_in[NE];             // CSR by target: source ids
__device__ int   g_dst_out[NE];            // CSR by source: target ids
__device__ float g_dinv1[NN], g_dinv2[NN];
__device__ float g_adj[KC * KC];

// ---------------- init ----------------
__global__ void k_zero() {
    int i = blockIdx.x * blockDim.x + threadIdx.x;
    int stride = gridDim.x * blockDim.x;
    for (int j = i; j < NN; j += stride) {
        g_deg_in[j] = 0; g_deg_out[j] = 0;
        g_cur_in[j] = 0; g_cur_out[j] = 0;
    }
    if (i < KC * KC) g_adj[i] = 0.f;
    if (i < FIN) g_cs[i] = 0.f;
}

__global__ void k_degree(const int* __restrict__ e) {
    int i = blockIdx.x * blockDim.x + threadIdx.x;
    int stride = gridDim.x * blockDim.x;
    for (int j = i; j < NE; j += stride) {
        atomicAdd(&g_deg_out[e[j]], 1);
        atomicAdd(&g_deg_in[e[NE + j]], 1);
    }
}

// ---- tiled block scan: block 0 scans deg_in, block 1 scans deg_out ----
__global__ __launch_bounds__(1024) void k_scan2() {
    const int* cnt = blockIdx.x ? g_deg_out : g_deg_in;
    int* off = blockIdx.x ? g_off_out : g_off_in;
    __shared__ int wsum[32];
    __shared__ int carry;
    int t = threadIdx.x;
    int lane = t & 31, w = t >> 5;
    if (t == 0) carry = 0;
    __syncthreads();
    for (int base = 0; base < NN; base += 1024) {
        int idx = base + t;
        int v = (idx < NN) ? cnt[idx] : 0;
        int x = v;
        #pragma unroll
        for (int o = 1; o < 32; o <<= 1) {
            int y = __shfl_up_sync(0xffffffffu, x, o);
            if (lane >= o) x += y;
        }
        if (lane == 31) wsum[w] = x;
        __syncthreads();
        if (w == 0) {
            int s = wsum[lane];
            #pragma unroll
            for (int o = 1; o < 32; o <<= 1) {
                int y = __shfl_up_sync(0xffffffffu, s, o);
                if (lane >= o) s += y;
            }
            wsum[lane] = s;
        }
        __syncthreads();
        int incl = x + (w ? wsum[w - 1] : 0);
        if (idx < NN) off[idx] = carry + incl - v;
        int total = wsum[31];
        __syncthreads();
        if (t == 0) carry += total;
        __syncthreads();
    }
    if (t == 0) off[NN] = carry;
}

__global__ void k_dinv() {
    int i = blockIdx.x * blockDim.x + threadIdx.x;
    int stride = gridDim.x * blockDim.x;
    for (int j = i; j < NN; j += stride) {
        g_dinv1[j] = rsqrtf((float)(g_deg_in[j] + 1)); // self-loop included
        int d = g_deg_out[j];
        g_dinv2[j] = (d > 0) ? rsqrtf((float)d) : 0.f;
    }
}

__global__ void k_fill(const int* __restrict__ e) {
    int i = blockIdx.x * blockDim.x + threadIdx.x;
    int stride = gridDim.x * blockDim.x;
    for (int j = i; j < NE; j += stride) {
        int r = e[j];
        int c = e[NE + j];
        int p = atomicAdd(&g_cur_in[c], 1);
        g_src_in[g_off_in[c] + p] = r;
        int q = atomicAdd(&g_cur_out[r], 1);
        g_dst_out[g_off_out[r] + q] = c;
    }
}

// ---------------- Wc = W1 @ fc1W  (128x256 @ 256x128) ----------------
__global__ __launch_bounds__(128) void k_wc(
    const float* __restrict__ W1, const float* __restrict__ fc1W)
{
    __shared__ float w1s[8][16];
    int f0 = blockIdx.x * 16;
    int tid = threadIdx.x; // d2 column
    float acc[16];
    #pragma unroll
    for (int f = 0; f < 16; f++) acc[f] = 0.f;
    for (int k0 = 0; k0 < D1; k0 += 8) {
        int kk = tid >> 4, ff = tid & 15;
        w1s[kk][ff] = W1[(size_t)(f0 + ff) * D1 + k0 + kk];
        __syncthreads();
        #pragma unroll
        for (int k = 0; k < 8; k++) {
            float b = fc1W[(size_t)(k0 + k) * D2 + tid];
            #pragma unroll
            for (int f = 0; f < 16; f++) acc[f] += w1s[k][f] * b;
        }
        __syncthreads();
    }
    #pragma unroll
    for (int f = 0; f < 16; f++) g_Wc[(size_t)(f0 + f) * D2 + tid] = acc[f];
}

// bc = b1 @ fc1W + fc1b
__global__ __launch_bounds__(128) void k_bc(
    const float* __restrict__ b1, const float* __restrict__ fc1W,
    const float* __restrict__ fc1b)
{
    int t = threadIdx.x;
    float acc = fc1b[t];
    for (int k = 0; k < D1; k++) acc += b1[k] * fc1W[(size_t)k * D2 + t];
    g_bc[t] = acc;
}

// ---------------- feature aggregation: aggX[i] = di*(sum ds*X[s] + di*X[i]) ----------------
__global__ __launch_bounds__(256) void k_agg(const float* __restrict__ X) {
    int i = blockIdx.x * 8 + (threadIdx.x >> 5);
    int lane = threadIdx.x & 31;
    if (i >= NN) return;
    float di = g_dinv1[i];
    const float4* X4 = (const float4*)X;
    float4 x = X4[(size_t)i * 32 + lane];
    float4 acc = make_float4(di * x.x, di * x.y, di * x.z, di * x.w);
    int s0 = g_off_in[i], s1 = g_off_in[i + 1];
    for (int idx = s0; idx < s1; idx++) {
        int s = g_src_in[idx];
        float ds = g_dinv1[s];
        float4 xs = X4[(size_t)s * 32 + lane];
        acc.x += ds * xs.x; acc.y += ds * xs.y;
        acc.z += ds * xs.z; acc.w += ds * xs.w;
    }
    float4 o = make_float4(di * acc.x, di * acc.y, di * acc.z, di * acc.w);
    ((float4*)g_aggX)[(size_t)i * 32 + lane] = o;
}

// ---------------- SGEMM: 128x128 tile, BK=8, 256 threads, 8x8 microtile ----------------
// abs = tanh(aggX @ Wc + bc)   M=NN, N=128, K=128
__global__ __launch_bounds__(256) void k_gemm_abs() {
    const float* __restrict__ A = g_aggX;
    const float* __restrict__ B = g_Wc;
    __shared__ float As[8][128];
    __shared__ float Bs[8][128];
    int tid = threadIdx.x;
    int m0 = blockIdx.y * 128;
    int tx = tid % 16, ty = tid / 16;

    int ar = tid >> 1, ak = (tid & 1) * 4;
    int bk = tid >> 5, bn = (tid & 31) * 4;

    float acc[8][8];
    #pragma unroll
    for (int i = 0; i < 8; i++)
        #pragma unroll
        for (int j = 0; j < 8; j++) acc[i][j] = 0.f;

    for (int k0 = 0; k0 < FIN; k0 += 8) {
        float4 av = make_float4(0.f, 0.f, 0.f, 0.f);
        if (m0 + ar < NN) av = *(const float4*)&A[(size_t)(m0 + ar) * FIN + k0 + ak];
        As[ak + 0][ar] = av.x; As[ak + 1][ar] = av.y;
        As[ak + 2][ar] = av.z; As[ak + 3][ar] = av.w;
        float4 bv = *(const float4*)&B[(size_t)(k0 + bk) * D2 + bn];
        *(float4*)&Bs[bk][bn] = bv;
        __syncthreads();
        #pragma unroll
        for (int k = 0; k < 8; k++) {
            float4 a0 = *(const float4*)&As[k][ty * 8];
            float4 a1 = *(const float4*)&As[k][ty * 8 + 4];
            float4 b0 = *(const float4*)&Bs[k][tx * 8];
            float4 b1 = *(const float4*)&Bs[k][tx * 8 + 4];
            float aR[8] = {a0.x, a0.y, a0.z, a0.w, a1.x, a1.y, a1.z, a1.w};
            float bR[8] = {b0.x, b0.y, b0.z, b0.w, b1.x, b1.y, b1.z, b1.w};
            #pragma unroll
            for (int i = 0; i < 8; i++)
                #pragma unroll
                for (int j = 0; j < 8; j++)
                    acc[i][j] += aR[i] * bR[j];
        }
        __syncthreads();
    }

    float bloc[8];
    #pragma unroll
    for (int j = 0; j < 8; j++) bloc[j] = g_bc[tx * 8 + j];
    #pragma unroll
    for (int i = 0; i < 8; i++) {
        int m = m0 + ty * 8 + i;
        if (m >= NN) continue;
        float v[8];
        #pragma unroll
        for (int j = 0; j < 8; j++) v[j] = tanhf(acc[i][j] + bloc[j]);
        *(float4*)&g_abs[(size_t)m * D2 + tx * 8] = make_float4(v[0], v[1], v[2], v[3]);
        *(float4*)&g_abs[(size_t)m * D2 + tx * 8 + 4] = make_float4(v[4], v[5], v[6], v[7]);
    }
}

// ---------------- fused fc2 + softmax ----------------
__global__ __launch_bounds__(256) void k_fc2_softmax(
    const float* __restrict__ W, const float* __restrict__ b)
{
    __shared__ float Ws[D2 * KC];
    __shared__ float bs[KC];
    int tid = threadIdx.x;
    for (int j = tid; j < D2 * KC; j += blockDim.x) Ws[j] = W[j];
    if (tid < KC) bs[tid] = b[tid];
    __syncthreads();
    int lane = tid & 31, warp = tid >> 5;
    int nwarps = (blockDim.x >> 5) * gridDim.x;
    for (int i = blockIdx.x * (blockDim.x >> 5) + warp; i < NN; i += nwarps) {
        float areg[4];
        #pragma unroll
        for (int j = 0; j < 4; j++) areg[j] = g_abs[(size_t)i * D2 + j * 32 + lane];
        float acc = bs[lane];
        #pragma unroll
        for (int j = 0; j < 4; j++)
            #pragma unroll
            for (int d = 0; d < 32; d++) {
                float a = __shfl_sync(0xffffffffu, areg[j], d);
                acc += a * Ws[(j * 32 + d) * KC + lane];
            }
        float m = acc;
        #pragma unroll
        for (int o = 16; o > 0; o >>= 1) m = fmaxf(m, __shfl_xor_sync(0xffffffffu, m, o));
        float e = expf(acc - m);
        float s = e;
        #pragma unroll
        for (int o = 16; o > 0; o >>= 1) s += __shfl_xor_sync(0xffffffffu, s, o);
        g_S[(size_t)i * KC + lane] = e / s;
    }
}

// ---------------- Laplacian: LS[i] = S[i] - dinv2[i]*sum dinv2[c]*S[c] ----------------
__global__ __launch_bounds__(256) void k_lap() {
    int tid = blockIdx.x * blockDim.x + threadIdx.x;
    int lane = tid & 31;
    int i = tid >> 5;
    if (i >= NN) return;
    float acc = g_S[(size_t)i * KC + lane];
    float di = g_dinv2[i];
    int s0 = g_off_out[i], s1 = g_off_out[i + 1];
    for (int idx = s0; idx < s1; idx++) {
        int c = g_dst_out[idx];
        acc -= di * g_dinv2[c] * g_S[(size_t)c * KC + lane];
    }
    g_LS[(size_t)i * KC + lane] = acc;
}

// ---------------- new_adj = S^T @ LS ----------------
__global__ __launch_bounds__(256) void k_adj() {
    __shared__ float sh[8][KC * KC];
    int tid = threadIdx.x, lane = tid & 31, w = tid >> 5;
    float acc[32];
    #pragma unroll
    for (int a = 0; a < 32; a++) acc[a] = 0.f;
    int gw = blockIdx.x * 8 + w, tw = gridDim.x * 8;
    for (int i = gw; i < NN; i += tw) {
        float sv = g_S[(size_t)i * 32 + lane];
        float lv = g_LS[(size_t)i * 32 + lane];
        #pragma unroll
        for (int a = 0; a < 32; a++) {
            float sa = __shfl_sync(0xffffffffu, sv, a);
            acc[a] += sa * lv;
        }
    }
    #pragma unroll
    for (int a = 0; a < 32; a++) sh[w][a * 32 + lane] = acc[a];
    __syncthreads();
    for (int j = tid; j < KC * KC; j += blockDim.x) {
        float s = 0.f;
        #pragma unroll
        for (int w2 = 0; w2 < 8; w2++) s += sh[w2][j];
        atomicAdd(&g_adj[j], s);
    }
}

// ---------------- column sum of aggX ----------------
__global__ __launch_bounds__(128) void k_colsum() {
    int t = threadIdx.x; // 128 = FIN
    float acc = 0.f;
    for (int i = blockIdx.x; i < NN; i += gridDim.x)
        acc += g_aggX[(size_t)i * FIN + t];
    atomicAdd(&g_cs[t], acc);
}

// ---------------- finalize: emb = (cs@W1 + NN*b1)/32 ; pos_penalty ----------------
__global__ void k_final(const float* __restrict__ W1, const float* __restrict__ b1,
                        float* __restrict__ out, int out_size) {
    int t = threadIdx.x; // 256 = D1
    float acc = (float)NN * b1[t];
    for (int f = 0; f < FIN; f++) acc += g_cs[f] * W1[(size_t)f * D1 + t];
    if (t < out_size) out[t] = acc * (1.f / 32.f);
    if (t < 32) {
        float rs = 0.f;
        #pragma unroll
        for (int b = 0; b < 32; b++) rs += fabsf(g_adj[t * 32 + b]);
        float d = g_adj[t * 33] / fmaxf(rs, 1e-12f);
        float contrib = (d - 1.f) * (d - 1.f) + 31.f * d * d;
        #pragma unroll
        for (int o = 16; o > 0; o >>= 1) contrib += __shfl_xor_sync(0xffffffffu, contrib, o);
        if (t == 0 && out_size > D1) out[D1] = contrib * (1.f / 1024.f);
    }
}

// ---------------- launch ----------------
extern "C" void kernel_launch(void* const* d_in, const int* in_sizes, int n_in,
                              void* d_out, int out_size) {
    const float* feat  = (const float*)d_in[0];
    const int*   edges = (const int*)d_in[1];   // (2, E) int32
    const float* W1    = (const float*)d_in[2];
    const float* b1    = (const float*)d_in[3];
    const float* fc1W  = (const float*)d_in[4];
    const float* fc1b  = (const float*)d_in[5];
    const float* fc2W  = (const float*)d_in[6];
    const float* fc2b  = (const float*)d_in[7];
    float* out = (float*)d_out;

    k_zero<<<256, 256>>>();
    k_degree<<<1024, 256>>>(edges);
    k_scan2<<<2, 1024>>>();
    k_dinv<<<256, 256>>>();
    k_fill<<<1024, 256>>>(edges);

    k_wc<<<8, 128>>>(W1, fc1W);
    k_bc<<<1, 128>>>(b1, fc1W, fc1b);
    k_agg<<<(NN + 7) / 8, 256>>>(feat);
    {
        dim3 grid(1, (NN + 127) / 128);
        k_gemm_abs<<<grid, 256>>>();
    }
    k_fc2_softmax<<<296, 256>>>(fc2W, fc2b);
    k_lap<<<(NN * 32 + 255) / 256, 256>>>();
    k_adj<<<148, 256>>>();
    k_colsum<<<512, 128>>>();
    k_final<<<1, 256>>>(W1, b1, out, out_size);
}